// round 7
// baseline (speedup 1.0000x reference)
#include <cuda_runtime.h>
#include <cstdint>

#define CH 128
#define BATCH 8
#define DIM 32
#define PLANE 1024
#define VOL 32768
#define APAD 132

__device__ __align__(16) float g_xs[(size_t)BATCH*VOL*CH];  // [b][z][y][x][ic'] scaled tf32
__device__ __align__(16) float g_wt[27*CH*CH];              // [tap][oc][ic'] tf32
__device__ float g_dm[BATCH*CH];

__device__ __forceinline__ float tf32r(float v){
    uint32_t u; asm("cvt.rna.tf32.f32 %0, %1;":"=r"(u):"f"(v));
    return __uint_as_float(u);
}
__device__ __forceinline__ int perm8(int i){
    return (i & ~7) | (((i & 3) << 1) | ((i >> 2) & 1));
}
__device__ __forceinline__ uint32_t s2u(const void* p){
    uint32_t a;
    asm("{ .reg .u64 t; cvta.to.shared.u64 t, %1; cvt.u32.u64 %0, t; }":"=r"(a):"l"(p));
    return a;
}
__device__ __forceinline__ void cpa16(uint32_t d, const void* s, bool ok){
    if(ok) asm volatile("cp.async.cg.shared.global [%0],[%1],16;"::"r"(d),"l"(s):"memory");
    else   asm volatile("cp.async.cg.shared.global [%0],[%1],16,0;"::"r"(d),"l"(s):"memory");
}
#define CPCOMMIT() asm volatile("cp.async.commit_group;":::"memory")
#define CPWAIT(n)  asm volatile("cp.async.wait_group %0;"::"n"(n):"memory")
#define MMA(c, a0,a1,a2,a3, b0,b1) \
    asm volatile("mma.sync.aligned.m16n8k8.row.col.f32.tf32.tf32.f32 " \
        "{%0,%1,%2,%3}, {%4,%5,%6,%7}, {%8,%9}, {%0,%1,%2,%3};" \
        : "+f"((c)[0]),"+f"((c)[1]),"+f"((c)[2]),"+f"((c)[3]) \
        : "r"(a0),"r"(a1),"r"(a2),"r"(a3),"r"(b0),"r"(b1))

// ---- prep: weights [o][i][27] -> g_wt[tap][o][perm8(i)], tf32 ----
__global__ void wprep(const float* __restrict__ w){
    int id = blockIdx.x*256 + threadIdx.x;
    if(id >= 27*CH*CH) return;
    int t = id / (CH*CH), r = id % (CH*CH), o = r >> 7, i = r & 127;
    g_wt[(size_t)t*16384 + o*128 + perm8(i)] = tf32r(w[(size_t)(o*128+i)*27 + t]);
}
// ---- prep: x -> scaled tf32, slot-major [b,z,y,x][perm8(ic)] ----
__global__ void xprep(const float* __restrict__ x, const float* __restrict__ ym){
    __shared__ float t[128][33];
    int b = blockIdx.z, z = blockIdx.y, yy = blockIdx.x;
    const float* xp = x + (size_t)b*CH*VOL + z*PLANE + yy*DIM;
    for(int r=0;r<16;r++){ int idx=r*256+threadIdx.x; int i=idx>>5, xx=idx&31;
        t[i][xx] = tf32r((1.f+ym[b*CH+i]) * xp[(size_t)i*VOL+xx]); }
    __syncthreads();
    float* op = g_xs + (size_t)(((b*DIM+z)*DIM+yy)*DIM)*CH;
    for(int r=0;r<16;r++){ int idx=r*256+threadIdx.x; int xx=idx>>7, i=idx&127;
        op[(size_t)xx*CH + perm8(i)] = t[i][xx]; }
}
// ---- prep: demod (fp32 exact) ----
__global__ void demod(const float* __restrict__ ym, const float* __restrict__ w){
    int o = blockIdx.x, b = blockIdx.y, i = threadIdx.x;
    float s = 1.f + ym[b*CH+i];
    const float* wp = w + (size_t)(o*128+i)*27;
    float a = 0.f;
    #pragma unroll
    for(int k=0;k<27;k++){ float v = wp[k]; a += v*v; }
    a *= s*s;
    __shared__ float red[128];
    red[i] = a; __syncthreads();
    #pragma unroll
    for(int off=64; off>0; off>>=1){ if(i<off) red[i]+=red[i+off]; __syncthreads(); }
    if(i==0) g_dm[b*CH+o] = rsqrtf(red[0] + 1e-8f);
}

// ---- conv: mma.sync tf32 implicit GEMM, 512 thr / 16 warps (4M x 4N) ----
// smem floats: A[136*132]=17952 @0 ; B0 @17952 ; B1 @34848 ; total 51744 f = 206976 B
#define AOFF 0
#define B0OFF 17952
#define BSZ   16896
#define DYNSM 206976
__global__ void __launch_bounds__(512,1) conv(float* __restrict__ out){
    extern __shared__ __align__(16) float sf[];
    const uint32_t S = s2u(sf);
    const int tid = threadIdx.x;
    const int rb = blockIdx.x, z = blockIdx.y, b = blockIdx.z;
    const int r0 = rb*4;
    const int wid = tid>>5, l = tid&31;
    const int wm = wid&3, wn = wid>>2;     // 4x4 warp grid, 32x32 warp tile
    const int g4 = l>>2, t4 = l&3;

    auto stageA = [&](int g){
        int dz = g/3, dy = g%3;
        int zz = z + dz - 1;
        bool zok = (unsigned)zz < 32u;
        const float* base = g_xs + ((size_t)(b*DIM + (zok?zz:0)) * PLANE) * CH;
        for(int c=tid; c<4352; c+=512){
            int slot = c>>5, part = c&31;
            int jr = slot/34, xi = slot - jr*34;
            int yy = r0 + jr + dy - 1, xx = xi - 1;
            bool ok = zok && ((unsigned)yy < 32u) && ((unsigned)xx < 32u);
            const float* src = base + (size_t)((ok?yy:0)*DIM + (ok?xx:0))*CH + part*4;
            cpa16(S + (uint32_t)(slot*APAD + part*4)*4, src, ok);
        }
    };
    auto stageB = [&](int t, int buf){
        const float* src = g_wt + (size_t)t*16384;
        uint32_t dst = S + (uint32_t)(B0OFF + buf*BSZ)*4;
        for(int c=tid; c<4096; c+=512){
            int o = c>>5, part = c&31;
            cpa16(dst + (uint32_t)(o*APAD + part*4)*4, src + o*128 + part*4, true);
        }
    };

    // per-lane fragment bases (mapping identical to R5, proven correct)
    int arow[2], boff[4];
    #pragma unroll
    for(int mi=0;mi<2;mi++){
        int mb = wm*32 + mi*16;
        arow[mi] = (mb>>5)*34 + (mb&31) + g4;     // + dx at use
    }
    #pragma unroll
    for(int ni=0;ni<4;ni++)
        boff[ni] = (wn*32 + ni*8 + g4)*APAD + 2*t4;

    float acc[2][4][4];
    #pragma unroll
    for(int mi=0;mi<2;mi++)
        #pragma unroll
        for(int ni=0;ni<4;ni++)
            #pragma unroll
            for(int e=0;e<4;e++) acc[mi][ni][e] = 0.f;

    // prologue
    stageA(0); CPCOMMIT();
    stageB(0,0); CPCOMMIT();
    stageB(1,1); CPCOMMIT();
    CPWAIT(1); __syncthreads();          // A0,B0 ready

    for(int t=0; t<27; t++){
        const int g = t/3, dx = t - g*3, buf = t&1;
        const float* Bp = sf + B0OFF + buf*BSZ;
        const float* A0 = sf + (arow[0]+dx)*APAD + 2*t4;
        const float* A1 = sf + (arow[1]+dx)*APAD + 2*t4;

        uint2 bf[2][4], al[2][2], ah[2][2];
        #pragma unroll
        for(int ni=0;ni<4;ni++) bf[0][ni] = *(const uint2*)(Bp + boff[ni]);
        al[0][0] = *(const uint2*)(A0);            ah[0][0] = *(const uint2*)(A0 + 8*APAD);
        al[0][1] = *(const uint2*)(A1);            ah[0][1] = *(const uint2*)(A1 + 8*APAD);

        #pragma unroll
        for(int kb=0; kb<16; kb++){
            const int cu = kb&1, nx = cu^1;
            if(kb < 15){
                const int ko = (kb+1)*8;
                #pragma unroll
                for(int ni=0;ni<4;ni++) bf[nx][ni] = *(const uint2*)(Bp + boff[ni] + ko);
                al[nx][0] = *(const uint2*)(A0 + ko);  ah[nx][0] = *(const uint2*)(A0 + ko + 8*APAD);
                al[nx][1] = *(const uint2*)(A1 + ko);  ah[nx][1] = *(const uint2*)(A1 + ko + 8*APAD);
            }
            #pragma unroll
            for(int mi=0;mi<2;mi++)
                #pragma unroll
                for(int ni=0;ni<4;ni++)
                    MMA(acc[mi][ni], al[cu][mi].x, ah[cu][mi].x, al[cu][mi].y, ah[cu][mi].y,
                        bf[cu][ni].x, bf[cu][ni].y);
        }
        if(t == 26) break;
        __syncthreads();                               // done reading B[buf] (and A at grp end)
        if(dx == 2 && g+1 < 9){ stageA(g+1); CPCOMMIT(); }
        if(t+2 < 27){ stageB(t+2, buf); CPCOMMIT(); }
        if(t+2 < 27){ CPWAIT(1); } else { CPWAIT(0); } // retire B_{t+1} (+A_{g+1})
        __syncthreads();
    }

    // epilogue: frags -> smem [oc][APAD], then demod + coalesced float4 stores
    __syncthreads();
    float* Cs = sf;   // 128*132 = 16896 floats <= 17952
    #pragma unroll
    for(int mi=0;mi<2;mi++){
        int mb = wm*32 + mi*16;
        #pragma unroll
        for(int ni=0;ni<4;ni++){
            int nb = wn*32 + ni*8 + 2*t4;
            Cs[(nb  )*APAD + mb + g4    ] = acc[mi][ni][0];
            Cs[(nb+1)*APAD + mb + g4    ] = acc[mi][ni][1];
            Cs[(nb  )*APAD + mb + g4 + 8] = acc[mi][ni][2];
            Cs[(nb+1)*APAD + mb + g4 + 8] = acc[mi][ni][3];
        }
    }
    __syncthreads();
    {
        int oc = tid>>2, q = tid&3;
        float d = g_dm[b*CH + oc];
        float* op = out + ((size_t)b*CH + oc)*VOL + z*PLANE + r0*32 + q*32;
        const float* cr = Cs + oc*APAD + q*32;
        #pragma unroll
        for(int j=0;j<8;j++){
            float4 v = *(const float4*)(cr + j*4);
            v.x *= d; v.y *= d; v.z *= d; v.w *= d;
            *(float4*)(op + j*4) = v;
        }
    }
}

extern "C" void kernel_launch(void* const* d_in, const int* in_sizes, int n_in,
                              void* d_out, int out_size){
    const float* x = (const float*)d_in[0];
    const float* y = (const float*)d_in[1];
    const float* w = (const float*)d_in[2];
    float* out = (float*)d_out;
    cudaFuncSetAttribute(conv, cudaFuncAttributeMaxDynamicSharedMemorySize, DYNSM);
    wprep<<<(27*CH*CH + 255)/256, 256>>>(w);
    xprep<<<dim3(32,32,8), 256>>>(x, y);
    demod<<<dim3(128,8), 128>>>(y, w);
    conv<<<dim3(8,32,8), 512, DYNSM>>>(out);
}

// round 8
// speedup vs baseline: 1.6644x; 1.6644x over previous
#include <cuda_runtime.h>
#include <cstdint>

#define CH 128
#define BATCH 8
#define DIM 32
#define PLANE 1024
#define VOL 32768
#define APAD 136

__device__ __align__(16) float g_xs[(size_t)BATCH*VOL*CH];  // [b][z][y][x][ic'] scaled tf32
__device__ __align__(16) float g_wt[27*CH*CH];              // [tap][oc][ic'] tf32
__device__ float g_dm[BATCH*CH];

__device__ __forceinline__ float tf32r(float v){
    uint32_t u; asm("cvt.rna.tf32.f32 %0, %1;":"=r"(u):"f"(v));
    return __uint_as_float(u);
}
__device__ __forceinline__ int perm8(int i){
    return (i & ~7) | (((i & 3) << 1) | ((i >> 2) & 1));
}
__device__ __forceinline__ uint32_t s2u(const void* p){
    uint32_t a;
    asm("{ .reg .u64 t; cvta.to.shared.u64 t, %1; cvt.u32.u64 %0, t; }":"=r"(a):"l"(p));
    return a;
}
__device__ __forceinline__ void cpa16(uint32_t d, const void* s, bool ok){
    if(ok) asm volatile("cp.async.cg.shared.global [%0],[%1],16;"::"r"(d),"l"(s):"memory");
    else   asm volatile("cp.async.cg.shared.global [%0],[%1],16,0;"::"r"(d),"l"(s):"memory");
}
#define CPCOMMIT() asm volatile("cp.async.commit_group;":::"memory")
#define CPWAIT(n)  asm volatile("cp.async.wait_group %0;"::"n"(n):"memory")
#define MMA(c, a0,a1,a2,a3, b0,b1) \
    asm volatile("mma.sync.aligned.m16n8k8.row.col.f32.tf32.tf32.f32 " \
        "{%0,%1,%2,%3}, {%4,%5,%6,%7}, {%8,%9}, {%0,%1,%2,%3};" \
        : "+f"((c)[0]),"+f"((c)[1]),"+f"((c)[2]),"+f"((c)[3]) \
        : "r"(a0),"r"(a1),"r"(a2),"r"(a3),"r"(b0),"r"(b1))

// ---- prep: weights [o][i][27] -> g_wt[tap][o][perm8(i)], tf32 ----
__global__ void wprep(const float* __restrict__ w){
    int id = blockIdx.x*256 + threadIdx.x;
    if(id >= 27*CH*CH) return;
    int t = id / (CH*CH), r = id % (CH*CH), o = r >> 7, i = r & 127;
    g_wt[(size_t)t*16384 + o*128 + perm8(i)] = tf32r(w[(size_t)(o*128+i)*27 + t]);
}
// ---- prep: x -> scaled tf32, slot-major [b,z,y,x][perm8(ic)] ----
__global__ void xprep(const float* __restrict__ x, const float* __restrict__ ym){
    __shared__ float t[128][33];
    int b = blockIdx.z, z = blockIdx.y, yy = blockIdx.x;
    const float* xp = x + (size_t)b*CH*VOL + z*PLANE + yy*DIM;
    for(int r=0;r<16;r++){ int idx=r*256+threadIdx.x; int i=idx>>5, xx=idx&31;
        t[i][xx] = tf32r((1.f+ym[b*CH+i]) * xp[(size_t)i*VOL+xx]); }
    __syncthreads();
    float* op = g_xs + (size_t)(((b*DIM+z)*DIM+yy)*DIM)*CH;
    for(int r=0;r<16;r++){ int idx=r*256+threadIdx.x; int xx=idx>>7, i=idx&127;
        op[(size_t)xx*CH + perm8(i)] = t[i][xx]; }
}
// ---- prep: demod (fp32 exact) ----
__global__ void demod(const float* __restrict__ ym, const float* __restrict__ w){
    int o = blockIdx.x, b = blockIdx.y, i = threadIdx.x;
    float s = 1.f + ym[b*CH+i];
    const float* wp = w + (size_t)(o*128+i)*27;
    float a = 0.f;
    #pragma unroll
    for(int k=0;k<27;k++){ float v = wp[k]; a += v*v; }
    a *= s*s;
    __shared__ float red[128];
    red[i] = a; __syncthreads();
    #pragma unroll
    for(int off=64; off>0; off>>=1){ if(i<off) red[i]+=red[i+off]; __syncthreads(); }
    if(i==0) g_dm[b*CH+o] = rsqrtf(red[0] + 1e-8f);
}

// ---- conv: mma.sync tf32 implicit GEMM, 256 thr / 8 warps (2M x 4N, 64x32 tile) ----
// smem floats: A[136*136]=18496 @0 ; B0 @18496 ; B1 @35904 ; total 53312 f = 213248 B
#define AOFF 0
#define B0OFF 18496
#define BSZ   17408
#define DYNSM 213248
__global__ void __launch_bounds__(256,1) conv(float* __restrict__ out){
    extern __shared__ __align__(16) float sf[];
    const uint32_t S = s2u(sf);
    const int tid = threadIdx.x;
    const int rb = blockIdx.x, z = blockIdx.y, b = blockIdx.z;
    const int r0 = rb*4;
    const int wid = tid>>5, l = tid&31;
    const int wm = wid&1, wn = wid>>1;
    const int g4 = l>>2, t4 = l&3;

    auto stageA = [&](int g){
        int dz = g/3, dy = g%3;
        int zz = z + dz - 1;
        bool zok = (unsigned)zz < 32u;
        const float* base = g_xs + ((size_t)(b*DIM + (zok?zz:0)) * PLANE) * CH;
        for(int c=tid; c<4352; c+=256){
            int slot = c>>5, part = c&31;
            int jr = slot/34, xi = slot - jr*34;
            int yy = r0 + jr + dy - 1, xx = xi - 1;
            bool ok = zok && ((unsigned)yy < 32u) && ((unsigned)xx < 32u);
            const float* src = base + (size_t)((ok?yy:0)*DIM + (ok?xx:0))*CH + part*4;
            cpa16(S + (uint32_t)(slot*APAD + part*4)*4, src, ok);
        }
    };
    auto stageB = [&](int t, int buf){
        const float* src = g_wt + (size_t)t*16384;
        uint32_t dst = S + (uint32_t)(B0OFF + buf*BSZ)*4;
        for(int c=tid; c<4096; c+=256){
            int o = c>>5, part = c&31;
            cpa16(dst + (uint32_t)(o*APAD + part*4)*4, src + o*128 + part*4, true);
        }
    };

    // per-lane fragment bases
    int arow[4], boff[4];
    #pragma unroll
    for(int mi=0;mi<4;mi++){
        int mb = wm*64 + mi*16;
        arow[mi] = (mb>>5)*34 + (mb&31) + g4;     // + dx at use
    }
    #pragma unroll
    for(int ni=0;ni<4;ni++)
        boff[ni] = (wn*32 + ni*8 + g4)*APAD + 2*t4;

    float acc[4][4][4];
    #pragma unroll
    for(int mi=0;mi<4;mi++)
        #pragma unroll
        for(int ni=0;ni<4;ni++)
            #pragma unroll
            for(int e=0;e<4;e++) acc[mi][ni][e] = 0.f;

    // prologue
    stageA(0); CPCOMMIT();
    stageB(0,0); CPCOMMIT();
    stageB(1,1); CPCOMMIT();
    CPWAIT(1); __syncthreads();          // A0,B0 ready

    for(int t=0; t<27; t++){
        const int g = t/3, dx = t - g*3, buf = t&1;
        const float* B = sf + B0OFF + buf*BSZ;
        const float* A = sf + AOFF;
        #pragma unroll
        for(int kb=0; kb<16; kb++){
            uint2 bf[4];
            #pragma unroll
            for(int ni=0;ni<4;ni++)
                bf[ni] = *(const uint2*)(B + boff[ni] + kb*8);
            #pragma unroll
            for(int mi=0;mi<4;mi++){
                const float* ap = A + (arow[mi]+dx)*APAD + kb*8 + 2*t4;
                uint2 alo = *(const uint2*)ap;
                uint2 ahi = *(const uint2*)(ap + 8*APAD);
                #pragma unroll
                for(int ni=0;ni<4;ni++)
                    MMA(acc[mi][ni], alo.x, ahi.x, alo.y, ahi.y, bf[ni].x, bf[ni].y);
            }
        }
        if(t == 26) break;
        __syncthreads();                               // done reading Bbuf[buf] (and A at grp end)
        if(dx == 2 && g+1 < 9){ stageA(g+1); CPCOMMIT(); }
        if(t+2 < 27){ stageB(t+2, buf); CPCOMMIT(); }
        if(t+2 < 27){ CPWAIT(1); } else { CPWAIT(0); } // retire B_{t+1} (+A_{g+1})
        __syncthreads();
    }

    // epilogue: frags -> smem [oc][APAD] over A region, then demod + coalesced store
    __syncthreads();
    float* Cs = sf;   // 128*136 = 17408 floats <= 18496
    #pragma unroll
    for(int mi=0;mi<4;mi++){
        int mb = wm*64 + mi*16;
        #pragma unroll
        for(int ni=0;ni<4;ni++){
            int nb = wn*32 + ni*8 + 2*t4;
            Cs[(nb  )*APAD + mb + g4    ] = acc[mi][ni][0];
            Cs[(nb+1)*APAD + mb + g4    ] = acc[mi][ni][1];
            Cs[(nb  )*APAD + mb + g4 + 8] = acc[mi][ni][2];
            Cs[(nb+1)*APAD + mb + g4 + 8] = acc[mi][ni][3];
        }
    }
    __syncthreads();
    {
        int oc = tid>>1, half = tid&1;
        float d = g_dm[b*CH + oc];
        float* op = out + ((size_t)b*CH + oc)*VOL + z*PLANE + r0*32 + half*64;
        const float* cr = Cs + oc*APAD + half*64;
        #pragma unroll
        for(int j=0;j<16;j++){
            float4 v = *(const float4*)(cr + j*4);
            v.x *= d; v.y *= d; v.z *= d; v.w *= d;
            *(float4*)(op + j*4) = v;
        }
    }
}

extern "C" void kernel_launch(void* const* d_in, const int* in_sizes, int n_in,
                              void* d_out, int out_size){
    const float* x = (const float*)d_in[0];
    const float* y = (const float*)d_in[1];
    const float* w = (const float*)d_in[2];
    float* out = (float*)d_out;
    cudaFuncSetAttribute(conv, cudaFuncAttributeMaxDynamicSharedMemorySize, DYNSM);
    wprep<<<(27*CH*CH + 255)/256, 256>>>(w);
    xprep<<<dim3(32,32,8), 256>>>(x, y);
    demod<<<dim3(128,8), 128>>>(y, w);
    conv<<<dim3(8,32,8), 256, DYNSM>>>(out);
}